// round 14
// baseline (speedup 1.0000x reference)
#include <cuda_runtime.h>
#include <cuda_bf16.h>
#include <math.h>

#define BB 64
#define LZ 128
#define EE 512
#define HH 512
#define VV 32000
#define TT 64
#define NVBLK 500            // logits blocks (64 v each)
#define KCH 32               // k-chunk size (elements)
#define NCHUNK (EE / KCH)    // 16

typedef unsigned long long ull;
typedef unsigned int u32;

// ---------------- device scratch ----------------
__device__ float g_hT[2][HH * BB];                 // hidden, k-major [k][b], double buffered
__device__ float g_xT[EE * BB];                    // GRU input x, k-major [k][b]
__device__ __align__(16) __nv_bfloat16 g_Whib[(size_t)VV * EE];  // W_fc bf16-hi [v][k]
__device__ __align__(16) __nv_bfloat16 g_Wlob[(size_t)VV * EE];  // W_fc bf16-lo [v][k]
__device__ __align__(16) __nv_bfloat16 g_hbhi[BB * HH];          // h bf16-hi, b-major [b][k]
__device__ __align__(16) __nv_bfloat16 g_hblo[BB * HH];          // h bf16-lo, b-major [b][k]
__device__ float2 g_pmax[BB][NVBLK];               // per-(batch, block) partial argmax

// ---------------- helpers ----------------
__device__ __forceinline__ void cp_async16(void* smem, const void* gmem) {
    u32 s = (u32)__cvta_generic_to_shared(smem);
    asm volatile("cp.async.cg.shared.global [%0], [%1], 16;\n" :: "r"(s), "l"(gmem));
}
__device__ __forceinline__ void cp_commit() {
    asm volatile("cp.async.commit_group;\n");
}
__device__ __forceinline__ void mma_bf16(float* c, const u32* a, u32 b0, u32 b1) {
    asm volatile(
        "mma.sync.aligned.m16n8k16.row.col.f32.bf16.bf16.f32 "
        "{%0,%1,%2,%3}, {%4,%5,%6,%7}, {%8,%9}, {%0,%1,%2,%3};"
        : "+f"(c[0]), "+f"(c[1]), "+f"(c[2]), "+f"(c[3])
        : "r"(a[0]), "r"(a[1]), "r"(a[2]), "r"(a[3]), "r"(b0), "r"(b1));
}

// ---------------- init: h0 = z @ W_proj^T + b_proj ----------------
__global__ void init_h_kernel(const float* __restrict__ z,
                              const float* __restrict__ Wp,
                              const float* __restrict__ bp) {
    int b = threadIdx.x;
    int j = blockIdx.x * 4 + threadIdx.y;
    float acc = 0.f;
    const float* zr = z + b * LZ;
    const float* wr = Wp + j * LZ;
#pragma unroll 4
    for (int l = 0; l < LZ; l++) acc += zr[l] * wr[l];
    acc += bp[j];
    g_hT[0][j * BB + b] = acc;
    g_xT[j * BB + b]    = acc;
}

// ---------------- split W_fc into bf16 hi/lo (once) ----------------
__global__ void split_wfc_kernel(const float* __restrict__ Wfc) {
    size_t i = ((size_t)blockIdx.x * 256 + threadIdx.x) * 4;
    float4 w = *(const float4*)(Wfc + i);
    __nv_bfloat16 h0 = __float2bfloat16(w.x);
    __nv_bfloat16 h1 = __float2bfloat16(w.y);
    __nv_bfloat16 h2 = __float2bfloat16(w.z);
    __nv_bfloat16 h3 = __float2bfloat16(w.w);
    __nv_bfloat16 l0 = __float2bfloat16(w.x - __bfloat162float(h0));
    __nv_bfloat16 l1 = __float2bfloat16(w.y - __bfloat162float(h1));
    __nv_bfloat16 l2 = __float2bfloat16(w.z - __bfloat162float(h2));
    __nv_bfloat16 l3 = __float2bfloat16(w.w - __bfloat162float(h3));
    *(__nv_bfloat162*)(g_Whib + i)     = __nv_bfloat162(h0, h1);
    *(__nv_bfloat162*)(g_Whib + i + 2) = __nv_bfloat162(h2, h3);
    *(__nv_bfloat162*)(g_Wlob + i)     = __nv_bfloat162(l0, l1);
    *(__nv_bfloat162*)(g_Wlob + i + 2) = __nv_bfloat162(l2, l3);
}

// ---------------- GRU cell, 8-way k-split ----------------
__global__ void __launch_bounds__(256) gru_kernel(const float* __restrict__ Wih,
                                                  const float* __restrict__ bih,
                                                  const float* __restrict__ Whh,
                                                  const float* __restrict__ bhh,
                                                  int cur) {
    int bp = threadIdx.x;
    int ks = threadIdx.y;
    int j  = blockIdx.x;

    const float4* wri = (const float4*)(Wih + (size_t)j * EE) + ks * 16;
    const float4* wzi = (const float4*)(Wih + (size_t)(j + HH) * EE) + ks * 16;
    const float4* wni = (const float4*)(Wih + (size_t)(j + 2 * HH) * EE) + ks * 16;
    const float4* wrh = (const float4*)(Whh + (size_t)j * HH) + ks * 16;
    const float4* wzh = (const float4*)(Whh + (size_t)(j + HH) * HH) + ks * 16;
    const float4* wnh = (const float4*)(Whh + (size_t)(j + 2 * HH) * HH) + ks * 16;

    const float* xcol = g_xT + 2 * bp + (size_t)(ks * 64) * BB;
    const float* hcol = g_hT[cur] + 2 * bp + (size_t)(ks * 64) * BB;

    float air0 = 0.f, air1 = 0.f, aiz0 = 0.f, aiz1 = 0.f, ain0 = 0.f, ain1 = 0.f;
    float ahr0 = 0.f, ahr1 = 0.f, ahz0 = 0.f, ahz1 = 0.f, ahn0 = 0.f, ahn1 = 0.f;

#pragma unroll 2
    for (int k4 = 0; k4 < 16; k4++) {
        float4 wa = wri[k4], wb = wzi[k4], wc = wni[k4];
        float4 wd = wrh[k4], we = wzh[k4], wf = wnh[k4];
#pragma unroll
        for (int s = 0; s < 4; s++) {
            int k = k4 * 4 + s;
            float2 x2 = *(const float2*)(xcol + (size_t)k * BB);
            float2 h2 = *(const float2*)(hcol + (size_t)k * BB);
            float wA = ((const float*)&wa)[s];
            float wB = ((const float*)&wb)[s];
            float wC = ((const float*)&wc)[s];
            float wD = ((const float*)&wd)[s];
            float wE = ((const float*)&we)[s];
            float wF = ((const float*)&wf)[s];
            air0 += wA * x2.x; air1 += wA * x2.y;
            aiz0 += wB * x2.x; aiz1 += wB * x2.y;
            ain0 += wC * x2.x; ain1 += wC * x2.y;
            ahr0 += wD * h2.x; ahr1 += wD * h2.y;
            ahz0 += wE * h2.x; ahz1 += wE * h2.y;
            ahn0 += wF * h2.x; ahn1 += wF * h2.y;
        }
    }

    __shared__ float2 sred[8][6][32];
    sred[ks][0][bp] = make_float2(air0, air1);
    sred[ks][1][bp] = make_float2(aiz0, aiz1);
    sred[ks][2][bp] = make_float2(ain0, ain1);
    sred[ks][3][bp] = make_float2(ahr0, ahr1);
    sred[ks][4][bp] = make_float2(ahz0, ahz1);
    sred[ks][5][bp] = make_float2(ahn0, ahn1);
    __syncthreads();

    if (ks == 0) {
        float g[6][2];
#pragma unroll
        for (int gi = 0; gi < 6; gi++) {
            float a0 = 0.f, a1 = 0.f;
#pragma unroll
            for (int s = 0; s < 8; s++) {
                float2 sv = sred[s][gi][bp];
                a0 += sv.x; a1 += sv.y;
            }
            g[gi][0] = a0; g[gi][1] = a1;
        }

        float bir = bih[j], biz = bih[j + HH], bin = bih[j + 2 * HH];
        float bhr = bhh[j], bhz = bhh[j + HH], bhn = bhh[j + 2 * HH];

        float2 hprev = *(const float2*)(g_hT[cur] + (size_t)j * BB + 2 * bp);
        float* hout = g_hT[1 - cur] + (size_t)j * BB + 2 * bp;

        float h0, h1;
        {
            float r  = 1.f / (1.f + expf(-((g[0][0] + bir) + (g[3][0] + bhr))));
            float zg = 1.f / (1.f + expf(-((g[1][0] + biz) + (g[4][0] + bhz))));
            float n  = tanhf((g[2][0] + bin) + r * (g[5][0] + bhn));
            h0 = (1.f - zg) * n + zg * hprev.x;
        }
        {
            float r  = 1.f / (1.f + expf(-((g[0][1] + bir) + (g[3][1] + bhr))));
            float zg = 1.f / (1.f + expf(-((g[1][1] + biz) + (g[4][1] + bhz))));
            float n  = tanhf((g[2][1] + bin) + r * (g[5][1] + bhn));
            h1 = (1.f - zg) * n + zg * hprev.y;
        }
        hout[0] = h0;
        hout[1] = h1;

        __nv_bfloat16 h0h = __float2bfloat16(h0);
        __nv_bfloat16 h1h = __float2bfloat16(h1);
        g_hbhi[(size_t)(2 * bp)     * HH + j] = h0h;
        g_hbhi[(size_t)(2 * bp + 1) * HH + j] = h1h;
        g_hblo[(size_t)(2 * bp)     * HH + j] = __float2bfloat16(h0 - __bfloat162float(h0h));
        g_hblo[(size_t)(2 * bp + 1) * HH + j] = __float2bfloat16(h1 - __bfloat162float(h1h));
    }
}

// ---------------- logits via bf16 3-term-split mma.sync, 8 warps ----------
// grid 500 (64 v per block), block 256 = 8 warps.
// warp (vq = wid>>1, half = wid&1): v rows vq*16..+15, batches half*32..+31.
// Per warp per chunk: 16 a-LDS + 32 b-LDS + 24 MMA -> 2x warps, same math,
// bit-identical per-logit accumulation order vs R12.
#define LROW 80
#define SMEM_DYN 40960

__global__ void __launch_bounds__(256, 4) logits_kernel(const float* __restrict__ bfc,
                                                        float* __restrict__ out,
                                                        int t) {
    extern __shared__ __align__(16) char smem[];
    int tid = threadIdx.x;
    int wid = tid >> 5;
    int lane = tid & 31;
    int g = lane >> 2;          // groupID
    int qk = lane & 3;          // thread-in-group
    int vq = wid >> 1;          // 0..3 -> v tile
    int half = wid & 1;         // 0..1 -> batch half
    int v0 = blockIdx.x * 64;

    const int OWHI[2] = {0, 5120};
    const int OWLO[2] = {10240, 15360};
    const int OBHI[2] = {20480, 25600};
    const int OBLO[2] = {30720, 35840};

    auto issue_chunk = [&](int c, int buf) {
        int kc = c * KCH;
        int row = tid >> 2, seg = tid & 3;          // 256 threads -> 64 rows x 4 segs
        cp_async16(smem + OWHI[buf] + row * LROW + seg * 16,
                   g_Whib + (size_t)(v0 + row) * EE + kc + seg * 8);
        cp_async16(smem + OWLO[buf] + row * LROW + seg * 16,
                   g_Wlob + (size_t)(v0 + row) * EE + kc + seg * 8);
        cp_async16(smem + OBHI[buf] + row * LROW + seg * 16,
                   g_hbhi + (size_t)row * HH + kc + seg * 8);
        cp_async16(smem + OBLO[buf] + row * LROW + seg * 16,
                   g_hblo + (size_t)row * HH + kc + seg * 8);
        cp_commit();
    };

    float acc[4][4];
#pragma unroll
    for (int n = 0; n < 4; n++)
#pragma unroll
        for (int i = 0; i < 4; i++) acc[n][i] = 0.f;

    issue_chunk(0, 0);
    issue_chunk(1, 1);

#pragma unroll 1
    for (int c = 0; c < NCHUNK; c++) {
        if (c < NCHUNK - 1) asm volatile("cp.async.wait_group 1;\n");
        else                asm volatile("cp.async.wait_group 0;\n");
        __syncthreads();

        const char* Wh = smem + OWHI[c & 1];
        const char* Wl = smem + OWLO[c & 1];
        const char* Bh = smem + OBHI[c & 1];
        const char* Bl = smem + OBLO[c & 1];

#pragma unroll
        for (int ks = 0; ks < 2; ks++) {
            int ko = ks * 32;                       // byte offset for 16 k
            u32 abase = (u32)((vq * 16 + g) * LROW + ko + qk * 4);
            u32 ahi[4], alo[4];
            ahi[0] = *(const u32*)(Wh + abase);
            ahi[1] = *(const u32*)(Wh + abase + 8 * LROW);
            ahi[2] = *(const u32*)(Wh + abase + 16);
            ahi[3] = *(const u32*)(Wh + abase + 8 * LROW + 16);
            alo[0] = *(const u32*)(Wl + abase);
            alo[1] = *(const u32*)(Wl + abase + 8 * LROW);
            alo[2] = *(const u32*)(Wl + abase + 16);
            alo[3] = *(const u32*)(Wl + abase + 8 * LROW + 16);

#pragma unroll
            for (int n = 0; n < 4; n++) {
                int nn = half * 4 + n;
                u32 bbase = (u32)((nn * 8 + g) * LROW + ko + qk * 4);
                u32 bhi0 = *(const u32*)(Bh + bbase);
                u32 bhi1 = *(const u32*)(Bh + bbase + 16);
                u32 blo0 = *(const u32*)(Bl + bbase);
                u32 blo1 = *(const u32*)(Bl + bbase + 16);
                mma_bf16(acc[n], ahi, bhi0, bhi1);
                mma_bf16(acc[n], ahi, blo0, blo1);
                mma_bf16(acc[n], alo, bhi0, bhi1);
            }
        }

        __syncthreads();
        if (c + 2 < NCHUNK) issue_chunk(c + 2, c & 1);
    }

    // stage D to smem [64v][66 fp32] (aliases stage buffers; all compute done)
    __syncthreads();
    float* sD = (float*)smem;
#pragma unroll
    for (int n = 0; n < 4; n++) {
        int b = half * 32 + n * 8 + qk * 2;
        int v = vq * 16 + g;
        *(float2*)(sD + v * 66 + b)       = make_float2(acc[n][0], acc[n][1]);
        *(float2*)(sD + (v + 8) * 66 + b) = make_float2(acc[n][2], acc[n][3]);
    }
    __syncthreads();

    // output + fused partial argmax: vg 4v x bg 4b per thread (256 threads)
    int vg = tid & 15;
    int bg = tid >> 4;
    int vA = v0 + vg * 4;
    float4 bias = *(const float4*)&bfc[vA];

#pragma unroll
    for (int i = 0; i < 4; i++) {
        int b = bg * 4 + i;
        float4 o;
        o.x = sD[(vg * 4 + 0) * 66 + b] + bias.x;
        o.y = sD[(vg * 4 + 1) * 66 + b] + bias.y;
        o.z = sD[(vg * 4 + 2) * 66 + b] + bias.z;
        o.w = sD[(vg * 4 + 3) * 66 + b] + bias.w;

        size_t rowoff = ((size_t)b * TT + t) * VV;
        __stcs((float4*)(out + rowoff + vA), o);

        float best = o.x; int bidx = vA;
        if (o.y > best) { best = o.y; bidx = vA + 1; }
        if (o.z > best) { best = o.z; bidx = vA + 2; }
        if (o.w > best) { best = o.w; bidx = vA + 3; }

#pragma unroll
        for (int m = 1; m < 16; m <<= 1) {
            float ov = __shfl_xor_sync(0xffffffffu, best, m);
            int   oi = __shfl_xor_sync(0xffffffffu, bidx, m);
            if (ov > best || (ov == best && oi < bidx)) { best = ov; bidx = oi; }
        }
        if (vg == 0)
            g_pmax[b][blockIdx.x] = make_float2(best, __int_as_float(bidx));
    }
}

// ---------------- final argmax + embedding gather ----------------
__global__ void argmax_embed_kernel(const float* __restrict__ emb) {
    int b = blockIdx.x;
    int tid = threadIdx.x;

    float best = -3.4e38f;
    int bidx = 0x7fffffff;
    for (int i = tid; i < NVBLK; i += 128) {
        float2 p = g_pmax[b][i];
        float v = p.x;
        int idx = __float_as_int(p.y);
        if (v > best || (v == best && idx < bidx)) { best = v; bidx = idx; }
    }

    __shared__ float sv[128];
    __shared__ int   si[128];
    sv[tid] = best; si[tid] = bidx;
    __syncthreads();
#pragma unroll
    for (int s = 64; s > 0; s >>= 1) {
        if (tid < s) {
            float ov = sv[tid + s]; int oi = si[tid + s];
            if (ov > sv[tid] || (ov == sv[tid] && oi < si[tid])) { sv[tid] = ov; si[tid] = oi; }
        }
        __syncthreads();
    }
    int id = si[0];

    const float* er = emb + (size_t)id * EE;
    for (int k = tid; k < EE; k += 128) g_xT[(size_t)k * BB + b] = er[k];
}

// ---------------- launch ----------------
extern "C" void kernel_launch(void* const* d_in, const int* in_sizes, int n_in,
                              void* d_out, int out_size) {
    const float* z     = (const float*)d_in[0];
    const float* emb   = (const float*)d_in[1];
    const float* Wproj = (const float*)d_in[2];
    const float* bproj = (const float*)d_in[3];
    const float* Wih   = (const float*)d_in[4];
    const float* bih   = (const float*)d_in[5];
    const float* Whh   = (const float*)d_in[6];
    const float* bhh   = (const float*)d_in[7];
    const float* Wfc   = (const float*)d_in[8];
    const float* bfc   = (const float*)d_in[9];
    float* out = (float*)d_out;

    cudaFuncSetAttribute(logits_kernel,
                         cudaFuncAttributeMaxDynamicSharedMemorySize, SMEM_DYN);

    init_h_kernel<<<128, dim3(64, 4)>>>(z, Wproj, bproj);
    split_wfc_kernel<<<(int)(((size_t)VV * EE / 4) / 256), 256>>>(Wfc);

    int cur = 0;
    for (int t = 0; t < TT; t++) {
        gru_kernel<<<512, dim3(32, 8)>>>(Wih, bih, Whh, bhh, cur);
        logits_kernel<<<NVBLK, 256, SMEM_DYN>>>(bfc, out, t);
        argmax_embed_kernel<<<64, 128>>>(emb);
        cur = 1 - cur;
    }
}

// round 16
// speedup vs baseline: 1.0152x; 1.0152x over previous
#include <cuda_runtime.h>
#include <cuda_bf16.h>
#include <math.h>

#define BB 64
#define LZ 128
#define EE 512
#define HH 512
#define VV 32000
#define TT 64
#define NVBLK 500            // logits blocks (64 v each)
#define KCH 32               // k-chunk size (elements)
#define NCHUNK (EE / KCH)    // 16

typedef unsigned long long ull;
typedef unsigned int u32;

// ---------------- device scratch ----------------
__device__ float g_hT[2][HH * BB];                 // hidden, k-major [k][b], double buffered
__device__ float g_xT[EE * BB];                    // GRU input x, k-major [k][b]
__device__ __align__(16) __nv_bfloat16 g_Whib[(size_t)VV * EE];  // W_fc bf16-hi [v][k]
__device__ __align__(16) __nv_bfloat16 g_Wlob[(size_t)VV * EE];  // W_fc bf16-lo [v][k]
__device__ __align__(16) __nv_bfloat16 g_hbhi[BB * HH];          // h bf16-hi, b-major [b][k]
__device__ __align__(16) __nv_bfloat16 g_hblo[BB * HH];          // h bf16-lo, b-major [b][k]
__device__ float2 g_pmax[BB][NVBLK];               // per-(batch, block) partial argmax

// ---------------- helpers ----------------
__device__ __forceinline__ void cp_async16(void* smem, const void* gmem) {
    u32 s = (u32)__cvta_generic_to_shared(smem);
    asm volatile("cp.async.cg.shared.global [%0], [%1], 16;\n" :: "r"(s), "l"(gmem));
}
__device__ __forceinline__ void cp_commit() {
    asm volatile("cp.async.commit_group;\n");
}
__device__ __forceinline__ void mma_bf16(float* c, const u32* a, u32 b0, u32 b1) {
    asm volatile(
        "mma.sync.aligned.m16n8k16.row.col.f32.bf16.bf16.f32 "
        "{%0,%1,%2,%3}, {%4,%5,%6,%7}, {%8,%9}, {%0,%1,%2,%3};"
        : "+f"(c[0]), "+f"(c[1]), "+f"(c[2]), "+f"(c[3])
        : "r"(a[0]), "r"(a[1]), "r"(a[2]), "r"(a[3]), "r"(b0), "r"(b1));
}

// ---------------- init: h0 = z @ W_proj^T + b_proj ----------------
__global__ void init_h_kernel(const float* __restrict__ z,
                              const float* __restrict__ Wp,
                              const float* __restrict__ bp) {
    int b = threadIdx.x;
    int j = blockIdx.x * 4 + threadIdx.y;
    float acc = 0.f;
    const float* zr = z + b * LZ;
    const float* wr = Wp + j * LZ;
#pragma unroll 4
    for (int l = 0; l < LZ; l++) acc += zr[l] * wr[l];
    acc += bp[j];
    g_hT[0][j * BB + b] = acc;
    g_xT[j * BB + b]    = acc;
}

// ---------------- split W_fc into bf16 hi/lo (once) ----------------
__global__ void split_wfc_kernel(const float* __restrict__ Wfc) {
    size_t i = ((size_t)blockIdx.x * 256 + threadIdx.x) * 4;
    float4 w = *(const float4*)(Wfc + i);
    __nv_bfloat16 h0 = __float2bfloat16(w.x);
    __nv_bfloat16 h1 = __float2bfloat16(w.y);
    __nv_bfloat16 h2 = __float2bfloat16(w.z);
    __nv_bfloat16 h3 = __float2bfloat16(w.w);
    __nv_bfloat16 l0 = __float2bfloat16(w.x - __bfloat162float(h0));
    __nv_bfloat16 l1 = __float2bfloat16(w.y - __bfloat162float(h1));
    __nv_bfloat16 l2 = __float2bfloat16(w.z - __bfloat162float(h2));
    __nv_bfloat16 l3 = __float2bfloat16(w.w - __bfloat162float(h3));
    *(__nv_bfloat162*)(g_Whib + i)     = __nv_bfloat162(h0, h1);
    *(__nv_bfloat162*)(g_Whib + i + 2) = __nv_bfloat162(h2, h3);
    *(__nv_bfloat162*)(g_Wlob + i)     = __nv_bfloat162(l0, l1);
    *(__nv_bfloat162*)(g_Wlob + i + 2) = __nv_bfloat162(l2, l3);
}

// ---------------- GRU cell, 8-way k-split ----------------
__global__ void __launch_bounds__(256) gru_kernel(const float* __restrict__ Wih,
                                                  const float* __restrict__ bih,
                                                  const float* __restrict__ Whh,
                                                  const float* __restrict__ bhh,
                                                  int cur) {
    int bp = threadIdx.x;
    int ks = threadIdx.y;
    int j  = blockIdx.x;

    const float4* wri = (const float4*)(Wih + (size_t)j * EE) + ks * 16;
    const float4* wzi = (const float4*)(Wih + (size_t)(j + HH) * EE) + ks * 16;
    const float4* wni = (const float4*)(Wih + (size_t)(j + 2 * HH) * EE) + ks * 16;
    const float4* wrh = (const float4*)(Whh + (size_t)j * HH) + ks * 16;
    const float4* wzh = (const float4*)(Whh + (size_t)(j + HH) * HH) + ks * 16;
    const float4* wnh = (const float4*)(Whh + (size_t)(j + 2 * HH) * HH) + ks * 16;

    const float* xcol = g_xT + 2 * bp + (size_t)(ks * 64) * BB;
    const float* hcol = g_hT[cur] + 2 * bp + (size_t)(ks * 64) * BB;

    float air0 = 0.f, air1 = 0.f, aiz0 = 0.f, aiz1 = 0.f, ain0 = 0.f, ain1 = 0.f;
    float ahr0 = 0.f, ahr1 = 0.f, ahz0 = 0.f, ahz1 = 0.f, ahn0 = 0.f, ahn1 = 0.f;

#pragma unroll 2
    for (int k4 = 0; k4 < 16; k4++) {
        float4 wa = wri[k4], wb = wzi[k4], wc = wni[k4];
        float4 wd = wrh[k4], we = wzh[k4], wf = wnh[k4];
#pragma unroll
        for (int s = 0; s < 4; s++) {
            int k = k4 * 4 + s;
            float2 x2 = *(const float2*)(xcol + (size_t)k * BB);
            float2 h2 = *(const float2*)(hcol + (size_t)k * BB);
            float wA = ((const float*)&wa)[s];
            float wB = ((const float*)&wb)[s];
            float wC = ((const float*)&wc)[s];
            float wD = ((const float*)&wd)[s];
            float wE = ((const float*)&we)[s];
            float wF = ((const float*)&wf)[s];
            air0 += wA * x2.x; air1 += wA * x2.y;
            aiz0 += wB * x2.x; aiz1 += wB * x2.y;
            ain0 += wC * x2.x; ain1 += wC * x2.y;
            ahr0 += wD * h2.x; ahr1 += wD * h2.y;
            ahz0 += wE * h2.x; ahz1 += wE * h2.y;
            ahn0 += wF * h2.x; ahn1 += wF * h2.y;
        }
    }

    __shared__ float2 sred[8][6][32];
    sred[ks][0][bp] = make_float2(air0, air1);
    sred[ks][1][bp] = make_float2(aiz0, aiz1);
    sred[ks][2][bp] = make_float2(ain0, ain1);
    sred[ks][3][bp] = make_float2(ahr0, ahr1);
    sred[ks][4][bp] = make_float2(ahz0, ahz1);
    sred[ks][5][bp] = make_float2(ahn0, ahn1);
    __syncthreads();

    if (ks == 0) {
        float g[6][2];
#pragma unroll
        for (int gi = 0; gi < 6; gi++) {
            float a0 = 0.f, a1 = 0.f;
#pragma unroll
            for (int s = 0; s < 8; s++) {
                float2 sv = sred[s][gi][bp];
                a0 += sv.x; a1 += sv.y;
            }
            g[gi][0] = a0; g[gi][1] = a1;
        }

        float bir = bih[j], biz = bih[j + HH], bin = bih[j + 2 * HH];
        float bhr = bhh[j], bhz = bhh[j + HH], bhn = bhh[j + 2 * HH];

        float2 hprev = *(const float2*)(g_hT[cur] + (size_t)j * BB + 2 * bp);
        float* hout = g_hT[1 - cur] + (size_t)j * BB + 2 * bp;

        float h0, h1;
        {
            float r  = 1.f / (1.f + expf(-((g[0][0] + bir) + (g[3][0] + bhr))));
            float zg = 1.f / (1.f + expf(-((g[1][0] + biz) + (g[4][0] + bhz))));
            float n  = tanhf((g[2][0] + bin) + r * (g[5][0] + bhn));
            h0 = (1.f - zg) * n + zg * hprev.x;
        }
        {
            float r  = 1.f / (1.f + expf(-((g[0][1] + bir) + (g[3][1] + bhr))));
            float zg = 1.f / (1.f + expf(-((g[1][1] + biz) + (g[4][1] + bhz))));
            float n  = tanhf((g[2][1] + bin) + r * (g[5][1] + bhn));
            h1 = (1.f - zg) * n + zg * hprev.y;
        }
        hout[0] = h0;
        hout[1] = h1;

        __nv_bfloat16 h0h = __float2bfloat16(h0);
        __nv_bfloat16 h1h = __float2bfloat16(h1);
        g_hbhi[(size_t)(2 * bp)     * HH + j] = h0h;
        g_hbhi[(size_t)(2 * bp + 1) * HH + j] = h1h;
        g_hblo[(size_t)(2 * bp)     * HH + j] = __float2bfloat16(h0 - __bfloat162float(h0h));
        g_hblo[(size_t)(2 * bp + 1) * HH + j] = __float2bfloat16(h1 - __bfloat162float(h1h));
    }
}

// ---------------- logits via bf16 split mma.sync, dual accumulators --------
// grid 500 (64 v per block), block 128 (4 warps; warp w owns v rows w*16..+15).
// accA = Whi*Bhi (depth-1 chains), accB = Whi*Blo + Wlo*Bhi (depth-2 chains):
// 16 independent accumulator chains per warp vs 8 -> hides HMMA latency.
#define LROW 80
#define SMEM_DYN 40960

__global__ void __launch_bounds__(128) logits_kernel(const float* __restrict__ bfc,
                                                     float* __restrict__ out,
                                                     int t) {
    extern __shared__ __align__(16) char smem[];
    int tid = threadIdx.x;
    int w = tid >> 5;
    int lane = tid & 31;
    int g = lane >> 2;          // groupID
    int qk = lane & 3;          // thread-in-group
    int v0 = blockIdx.x * 64;

    const int OWHI[2] = {0, 5120};
    const int OWLO[2] = {10240, 15360};
    const int OBHI[2] = {20480, 25600};
    const int OBLO[2] = {30720, 35840};

    auto issue_chunk = [&](int c, int buf) {
        int kc = c * KCH;
#pragma unroll
        for (int p = 0; p < 2; p++) {
            int lin = tid + p * 128;            // 0..255
            int row = lin >> 2, seg = lin & 3;
            cp_async16(smem + OWHI[buf] + row * LROW + seg * 16,
                       g_Whib + (size_t)(v0 + row) * EE + kc + seg * 8);
            cp_async16(smem + OWLO[buf] + row * LROW + seg * 16,
                       g_Wlob + (size_t)(v0 + row) * EE + kc + seg * 8);
            cp_async16(smem + OBHI[buf] + row * LROW + seg * 16,
                       g_hbhi + (size_t)row * HH + kc + seg * 8);
            cp_async16(smem + OBLO[buf] + row * LROW + seg * 16,
                       g_hblo + (size_t)row * HH + kc + seg * 8);
        }
        cp_commit();
    };

    float accA[8][4], accB[8][4];
#pragma unroll
    for (int n = 0; n < 8; n++)
#pragma unroll
        for (int i = 0; i < 4; i++) { accA[n][i] = 0.f; accB[n][i] = 0.f; }

    issue_chunk(0, 0);
    issue_chunk(1, 1);

#pragma unroll 1
    for (int c = 0; c < NCHUNK; c++) {
        if (c < NCHUNK - 1) asm volatile("cp.async.wait_group 1;\n");
        else                asm volatile("cp.async.wait_group 0;\n");
        __syncthreads();

        const char* Wh = smem + OWHI[c & 1];
        const char* Wl = smem + OWLO[c & 1];
        const char* Bh = smem + OBHI[c & 1];
        const char* Bl = smem + OBLO[c & 1];

#pragma unroll
        for (int ks = 0; ks < 2; ks++) {
            int ko = ks * 32;                       // byte offset for 16 k
            u32 abase = (u32)((w * 16 + g) * LROW + ko + qk * 4);
            u32 ahi[4], alo[4];
            ahi[0] = *(const u32*)(Wh + abase);
            ahi[1] = *(const u32*)(Wh + abase + 8 * LROW);
            ahi[2] = *(const u32*)(Wh + abase + 16);
            ahi[3] = *(const u32*)(Wh + abase + 8 * LROW + 16);
            alo[0] = *(const u32*)(Wl + abase);
            alo[1] = *(const u32*)(Wl + abase + 8 * LROW);
            alo[2] = *(const u32*)(Wl + abase + 16);
            alo[3] = *(const u32*)(Wl + abase + 8 * LROW + 16);

#pragma unroll
            for (int n = 0; n < 8; n++) {
                u32 bbase = (u32)((n * 8 + g) * LROW + ko + qk * 4);
                u32 bhi0 = *(const u32*)(Bh + bbase);
                u32 bhi1 = *(const u32*)(Bh + bbase + 16);
                u32 blo0 = *(const u32*)(Bl + bbase);
                u32 blo1 = *(const u32*)(Bl + bbase + 16);
                mma_bf16(accA[n], ahi, bhi0, bhi1);   // depth-1 chain
                mma_bf16(accB[n], ahi, blo0, blo1);   // depth-2 chain
                mma_bf16(accB[n], alo, bhi0, bhi1);
            }
        }

        __syncthreads();
        if (c + 2 < NCHUNK) issue_chunk(c + 2, c & 1);
    }

    // stage D = accA + accB to smem [64v][66 fp32] (aliases stage buffers)
    __syncthreads();
    float* sD = (float*)smem;
#pragma unroll
    for (int n = 0; n < 8; n++) {
        int b = n * 8 + qk * 2;
        int v = w * 16 + g;
        *(float2*)(sD + v * 66 + b) =
            make_float2(accA[n][0] + accB[n][0], accA[n][1] + accB[n][1]);
        *(float2*)(sD + (v + 8) * 66 + b) =
            make_float2(accA[n][2] + accB[n][2], accA[n][3] + accB[n][3]);
    }
    __syncthreads();

    // output + fused partial argmax: vg 4v, bg 8b per thread
    int vg = tid & 15;
    int bg = tid >> 4;
    int vA = v0 + vg * 4;
    float4 bias = *(const float4*)&bfc[vA];

#pragma unroll
    for (int i = 0; i < 8; i++) {
        int b = bg * 8 + i;
        float4 o;
        o.x = sD[(vg * 4 + 0) * 66 + b] + bias.x;
        o.y = sD[(vg * 4 + 1) * 66 + b] + bias.y;
        o.z = sD[(vg * 4 + 2) * 66 + b] + bias.z;
        o.w = sD[(vg * 4 + 3) * 66 + b] + bias.w;

        size_t rowoff = ((size_t)b * TT + t) * VV;
        __stcs((float4*)(out + rowoff + vA), o);

        float best = o.x; int bidx = vA;
        if (o.y > best) { best = o.y; bidx = vA + 1; }
        if (o.z > best) { best = o.z; bidx = vA + 2; }
        if (o.w > best) { best = o.w; bidx = vA + 3; }

#pragma unroll
        for (int m = 1; m < 16; m <<= 1) {
            float ov = __shfl_xor_sync(0xffffffffu, best, m);
            int   oi = __shfl_xor_sync(0xffffffffu, bidx, m);
            if (ov > best || (ov == best && oi < bidx)) { best = ov; bidx = oi; }
        }
        if (vg == 0)
            g_pmax[b][blockIdx.x] = make_float2(best, __int_as_float(bidx));
    }
}

// ---------------- final argmax + embedding gather ----------------
__global__ void argmax_embed_kernel(const float* __restrict__ emb) {
    int b = blockIdx.x;
    int tid = threadIdx.x;

    float best = -3.4e38f;
    int bidx = 0x7fffffff;
    for (int i = tid; i < NVBLK; i += 128) {
        float2 p = g_pmax[b][i];
        float v = p.x;
        int idx = __float_as_int(p.y);
        if (v > best || (v == best && idx < bidx)) { best = v; bidx = idx; }
    }

    __shared__ float sv[128];
    __shared__ int   si[128];
    sv[tid] = best; si[tid] = bidx;
    __syncthreads();
#pragma unroll
    for (int s = 64; s > 0; s >>= 1) {
        if (tid < s) {
            float ov = sv[tid + s]; int oi = si[tid + s];
            if (ov > sv[tid] || (ov == sv[tid] && oi < si[tid])) { sv[tid] = ov; si[tid] = oi; }
        }
        __syncthreads();
    }
    int id = si[0];

    const float* er = emb + (size_t)id * EE;
    for (int k = tid; k < EE; k += 128) g_xT[(size_t)k * BB + b] = er[k];
}

// ---------------- launch ----------------
extern "C" void kernel_launch(void* const* d_in, const int* in_sizes, int n_in,
                              void* d_out, int out_size) {
    const float* z     = (const float*)d_in[0];
    const float* emb   = (const float*)d_in[1];
    const float* Wproj = (const float*)d_in[2];
    const float* bproj = (const float*)d_in[3];
    const float* Wih   = (const float*)d_in[4];
    const float* bih   = (const float*)d_in[5];
    const float* Whh   = (const float*)d_in[6];
    const float* bhh   = (const float*)d_in[7];
    const float* Wfc   = (const float*)d_in[8];
    const float* bfc   = (const float*)d_in[9];
    float* out = (float*)d_out;

    init_h_kernel<<<128, dim3(64, 4)>>>(z, Wproj, bproj);
    split_wfc_kernel<<<(int)(((size_t)VV * EE / 4) / 256), 256>>>(Wfc);

    int cur = 0;
    for (int t = 0; t < TT; t++) {
        gru_kernel<<<512, dim3(32, 8)>>>(Wih, bih, Whh, bhh, cur);
        logits_kernel<<<NVBLK, 128, SMEM_DYN>>>(bfc, out, t);
        argmax_embed_kernel<<<64, 128>>>(emb);
        cur = 1 - cur;
    }
}